// round 7
// baseline (speedup 1.0000x reference)
#include <cuda_runtime.h>

// B=4, C=80, M=16 fixed by the reference; N derived at runtime (76725 @640x640).
#define BB 4
#define CC 80
#define C4 20            // float4 per anchor row
#define MM 16
#define TILE 256         // anchors per block (one per thread in phase 1)
#define THREADS 256

#define IMG_W 640.0f
#define IMG_H 640.0f
#define EPS_F 1e-4f
#define BETA_F (1.0f / 9.0f)
#define LN2_F 0.6931471805599453f

__device__ float        g_cls_sum[BB];
__device__ float        g_reg_sum[BB];
__device__ int          g_pos[BB];
__device__ unsigned int g_count = 0;

// FMA-pipe natural log (njuffa-style): exponent peel + log1p minimax on [2/3,4/3].
// Max relative error ~3e-5 — orders of magnitude inside the 1e-3 budget.
__device__ __forceinline__ float fast_lnf(float a) {
    const int   e = (__float_as_int(a) - 0x3f2aaaab) & 0xff800000;
    const float m = __int_as_float(__float_as_int(a) - e);
    const float i = (float)e * 1.19209290e-7f;   // e / 2^23
    const float f = m - 1.0f;
    const float s = f * f;
    float r = fmaf(0.230836749f, f, -0.279208571f);
    const float t = fmaf(0.331826031f, f, -0.498910338f);
    r = fmaf(r, s, t);
    r = fmaf(r, s, f);
    r = fmaf(i, 0.693147182f, r);
    return r;
}

__global__ void __launch_bounds__(THREADS, 4)
retina_fused_kernel(const float* __restrict__ cls,
                    const float* __restrict__ regs,
                    const float* __restrict__ anchors,
                    const float* __restrict__ annots,
                    float* __restrict__ out,
                    int N) {
    const int b   = blockIdx.y;
    const int n0  = blockIdx.x * TILE;
    const int tid = threadIdx.x;

    __shared__ float sann[MM * 5];
    __shared__ float sarea[MM];
    __shared__ float slab[TILE];
    __shared__ float swred[8][3];

    if (tid < MM * 5) sann[tid] = annots[b * MM * 5 + tid];
    __syncthreads();
    if (tid < MM) {
        sarea[tid] = (sann[tid * 5 + 2] - sann[tid * 5 + 0]) *
                     (sann[tid * 5 + 3] - sann[tid * 5 + 1]);
    }
    __syncthreads();

    // ---- Phase 1 (all 256 threads, one anchor each): division-free IoU argmax ----
    float my_reg = 0.0f;
    float my_pos = 0.0f;
    float my_cor = 0.0f;
    {
        const int n = n0 + tid;
        float label = -1.0f;
        if (n < N) {
            const long an = (long)b * N + n;
            const float4 a4 = reinterpret_cast<const float4*>(anchors)[an];
            const float a0 = a4.x, a1 = a4.y, a2 = a4.z, a3 = a4.w;
            const bool inside = (a0 > 0.0f) && (a1 > 0.0f) && (a2 < IMG_W) && (a3 < IMG_H);
            const float area_a = (a2 - a0) * (a3 - a1);

            float bnum = -1.0f, bden = 1.0f;   // best IoU as fraction (positive denom)
            int   bidx = 0;
            bool  anyv = false;
#pragma unroll
            for (int j = 0; j < MM; j++) {
                const float g0 = sann[j * 5 + 0];
                const float g1 = sann[j * 5 + 1];
                const float g2 = sann[j * 5 + 2];
                const float g3 = sann[j * 5 + 3];
                const bool valid = (sann[j * 5 + 4] >= 0.0f);
                anyv |= valid;
                const float lx = fmaxf(a0, g0), ly = fmaxf(a1, g1);
                const float rx = fminf(a2, g2), ry = fminf(a3, g3);
                const float wx = fmaxf(rx - lx, 0.0f), wy = fmaxf(ry - ly, 0.0f);
                const float num = wx * wy;
                const float den = area_a + sarea[j] - num;
                if (valid && (num * bden > bnum * den)) {
                    bnum = num; bden = den; bidx = j;
                }
            }

            if (bnum < 0.4f * bden) label = 0.0f;
            if (bnum > 0.5f * bden) label = sann[bidx * 5 + 4] + 1.0f;
            if (!anyv)   label = -1.0f;
            if (!inside) label = -1.0f;

            if (label > 0.0f) {
                const float g0 = sann[bidx * 5 + 0];
                const float g1 = sann[bidx * 5 + 1];
                const float g2 = sann[bidx * 5 + 2];
                const float g3 = sann[bidx * 5 + 3];
                const float aw = a2 - a0, ah = a3 - a1;
                const float acx = a0 + 0.5f * aw, acy = a1 + 0.5f * ah;
                const float gw = fmaxf(g2 - g0, 1.0f);
                const float gh = fmaxf(g3 - g1, 1.0f);
                const float gcx = g0 + 0.5f * gw, gcy = g1 + 0.5f * gh;
                const float t0 = ((gcx - acx) / aw) * 10.0f;
                const float t1 = ((gcy - acy) / ah) * 10.0f;
                const float t2 = __logf(gw / aw) * 5.0f;
                const float t3 = __logf(gh / ah) * 5.0f;

                const float4 r4 = reinterpret_cast<const float4*>(regs)[an];
                const float xs[4] = { fabsf(r4.x - t0), fabsf(r4.y - t1),
                                      fabsf(r4.z - t2), fabsf(r4.w - t3) };
#pragma unroll
                for (int k = 0; k < 4; k++) {
                    const float x = xs[k];
                    my_reg += (x < BETA_F) ? (0.5f * x * x / BETA_F) : (x - 0.5f * BETA_F);
                }
                my_pos = 1.0f;

                // correction: true positive focal term minus what the sweep adds for this class
                const int lp = (int)label - 1;
                const float pv = cls[an * CC + lp];
                const float p = fminf(fmaxf(pv, EPS_F), 1.0f - EPS_F);
                const float q = 1.0f - p;
                my_cor = 0.25f * q * q * (-__logf(p)) - 0.75f * pv * pv * (-__logf(1.0f - pv));
            }
        }
        slab[tid] = label;
    }
    __syncthreads();

    // ---- Phase 2: negative-focal sweep, MUFU/FMA hybrid (even k -> MUFU, odd k -> poly) ----
    const int al = tid >> 2;        // 0..63
    const int lc = tid & 3;
    const float4* __restrict__ base =
        reinterpret_cast<const float4*>(cls) + (long)b * N * C4 + (long)n0 * C4 + lc;

    float s_lg2 = 0.0f;   // sum pv^2 * lg2(1-pv)   (MUFU lane)
    float s_ln  = 0.0f;   // sum pv^2 * ln(1-pv)    (FMA-poly lane)
#pragma unroll
    for (int w = 0; w < 2; w++) {
        const int a0 = al + w * 128;
        const int a1 = a0 + 64;
        const bool u0 = (slab[a0] >= 0.0f);
        const bool u1 = (slab[a1] >= 0.0f);
        const float4* __restrict__ p0 = base + a0 * C4;
        const float4* __restrict__ p1 = base + a1 * C4;

        float4 v0[5], v1[5];
        if (u0) {
#pragma unroll
            for (int it = 0; it < 5; it++) v0[it] = p0[it * 4];
        }
        if (u1) {
#pragma unroll
            for (int it = 0; it < 5; it++) v1[it] = p1[it * 4];
        }

        if (u0) {
#pragma unroll
            for (int it = 0; it < 5; it++) {
                const float pv[4] = { v0[it].x, v0[it].y, v0[it].z, v0[it].w };
#pragma unroll
                for (int k = 0; k < 4; k += 2) {
                    s_lg2 = fmaf(pv[k]   * pv[k],   __log2f(1.0f - pv[k]),   s_lg2);
                    s_ln  = fmaf(pv[k+1] * pv[k+1], fast_lnf(1.0f - pv[k+1]), s_ln);
                }
            }
        }
        if (u1) {
#pragma unroll
            for (int it = 0; it < 5; it++) {
                const float pv[4] = { v1[it].x, v1[it].y, v1[it].z, v1[it].w };
#pragma unroll
                for (int k = 0; k < 4; k += 2) {
                    s_lg2 = fmaf(pv[k]   * pv[k],   __log2f(1.0f - pv[k]),   s_lg2);
                    s_ln  = fmaf(pv[k+1] * pv[k+1], fast_lnf(1.0f - pv[k+1]), s_ln);
                }
            }
        }
    }
    // focal negatives: 0.75 * pv^2 * (-ln(1-pv)) summed over all classes
    float acc = my_cor - 0.75f * fmaf(LN2_F, s_lg2, s_ln);

    // ---- Phase 3: warp shuffle reduce, one barrier, 3 atomics per block ----
#pragma unroll
    for (int o = 16; o; o >>= 1) {
        acc    += __shfl_down_sync(0xffffffffu, acc,    o);
        my_reg += __shfl_down_sync(0xffffffffu, my_reg, o);
        my_pos += __shfl_down_sync(0xffffffffu, my_pos, o);
    }
    const int wid = tid >> 5;
    if ((tid & 31) == 0) {
        swred[wid][0] = acc;
        swred[wid][1] = my_reg;
        swred[wid][2] = my_pos;
    }
    __syncthreads();
    if (tid == 0) {
        float c = 0.0f, r = 0.0f, p = 0.0f;
#pragma unroll
        for (int w = 0; w < 8; w++) {
            c += swred[w][0];
            r += swred[w][1];
            p += swred[w][2];
        }
        if (c != 0.0f) atomicAdd(&g_cls_sum[b], c);
        if (r != 0.0f) atomicAdd(&g_reg_sum[b], r);
        const int pi = (int)(p + 0.5f);
        if (pi) atomicAdd(&g_pos[b], pi);
    }

    // ---- Phase 4: last block finalizes + resets state for next replay ----
    __shared__ bool is_last;
    __threadfence();
    if (tid == 0) {
        const unsigned total = gridDim.x * gridDim.y;
        is_last = (atomicAdd(&g_count, 1u) == total - 1u);
    }
    __syncthreads();
    if (!is_last) return;

    if (tid == 0) {
        float cls_l = 0.0f, reg_l = 0.0f, nvalid = 0.0f;
#pragma unroll
        for (int bi = 0; bi < BB; bi++) {
            const float p = (float)g_pos[bi];
            if (p > 0.0f) {
                cls_l += g_cls_sum[bi] / p;
                reg_l += g_reg_sum[bi] / (4.0f * p);
                nvalid += 1.0f;
            }
            g_cls_sum[bi] = 0.0f;
            g_reg_sum[bi] = 0.0f;
            g_pos[bi] = 0;
        }
        nvalid = fmaxf(nvalid, 1.0f);
        out[0] = cls_l / nvalid;
        out[1] = reg_l / nvalid;
        g_count = 0;
    }
}

extern "C" void kernel_launch(void* const* d_in, const int* in_sizes, int n_in,
                              void* d_out, int out_size) {
    const float* cls     = (const float*)d_in[0];  // (B, N, C)
    const float* regs    = (const float*)d_in[1];  // (B, N, 4)
    const float* anchors = (const float*)d_in[2];  // (B, N, 4)
    const float* annots  = (const float*)d_in[3];  // (B, M, 5)

    const int N = in_sizes[1] / (BB * 4);
    const int numTiles = (N + TILE - 1) / TILE;

    dim3 grid(numTiles, BB);
    retina_fused_kernel<<<grid, THREADS>>>(cls, regs, anchors, annots,
                                           (float*)d_out, N);
}

// round 8
// speedup vs baseline: 1.2398x; 1.2398x over previous
#include <cuda_runtime.h>

// B=4, C=80, M=16 fixed by the reference; N derived at runtime (76725 @640x640).
#define BB 4
#define CC 80
#define C4 20            // float4 per anchor row
#define MM 16
#define TILE 256         // anchors per block (one per thread in phase 1)
#define THREADS 256

#define IMG_W 640.0f
#define IMG_H 640.0f
#define EPS_F 1e-4f
#define BETA_F (1.0f / 9.0f)
#define LN2_F 0.6931471805599453f

__device__ float        g_cls_sum[BB];
__device__ float        g_reg_sum[BB];
__device__ int          g_pos[BB];
__device__ unsigned int g_count = 0;

// Packed focal-negative step for an element pair (x,y):
// acc2.{lo,hi} += p^2 * lg2(1-p). 5 instructions per 2 elements if movs elide.
__device__ __forceinline__ void foc2(float x, float y,
                                     unsigned long long& acc2,
                                     unsigned long long nones,   // {-1,-1}
                                     unsigned long long ones) {  // { 1, 1}
    unsigned long long v2, u2, l2, sq2;
    asm("mov.b64 %0, {%1, %2};" : "=l"(v2) : "f"(x), "f"(y));
    asm("fma.rn.f32x2 %0, %1, %2, %3;" : "=l"(u2) : "l"(v2), "l"(nones), "l"(ones));
    float ulo, uhi, llo, lhi;
    asm("mov.b64 {%0, %1}, %2;" : "=f"(ulo), "=f"(uhi) : "l"(u2));
    asm("lg2.approx.f32 %0, %1;" : "=f"(llo) : "f"(ulo));
    asm("lg2.approx.f32 %0, %1;" : "=f"(lhi) : "f"(uhi));
    asm("mov.b64 %0, {%1, %2};" : "=l"(l2) : "f"(llo), "f"(lhi));
    asm("mul.rn.f32x2 %0, %1, %2;" : "=l"(sq2) : "l"(v2), "l"(v2));
    asm("fma.rn.f32x2 %0, %1, %2, %3;" : "=l"(acc2) : "l"(sq2), "l"(l2), "l"(acc2));
}

__global__ void __launch_bounds__(THREADS, 4)
retina_fused_kernel(const float* __restrict__ cls,
                    const float* __restrict__ regs,
                    const float* __restrict__ anchors,
                    const float* __restrict__ annots,
                    float* __restrict__ out,
                    int N) {
    const int b   = blockIdx.y;
    const int n0  = blockIdx.x * TILE;
    const int tid = threadIdx.x;

    __shared__ float4 sbox[MM];
    __shared__ float  sarea[MM];
    __shared__ float  scls[MM];
    __shared__ int    sanyv;
    __shared__ float  slab[TILE];
    __shared__ float  swred[8][3];

    // GT preprocessing: zero invalid boxes (iou becomes 0 -> can never win a
    // positive assignment), hoist anyv to one flag, precompute areas.
    if (tid < MM) {
        const float* g = annots + (b * MM + tid) * 5;
        float g0 = g[0], g1 = g[1], g2 = g[2], g3 = g[3], gc = g[4];
        const bool valid = (gc >= 0.0f);
        const unsigned bal = __ballot_sync(0x0000ffffu, valid);
        if (tid == 0) sanyv = (bal != 0u);
        if (!valid) { g0 = g1 = g2 = g3 = 0.0f; gc = 0.0f; }
        sbox[tid]  = make_float4(g0, g1, g2, g3);
        sarea[tid] = (g2 - g0) * (g3 - g1);
        scls[tid]  = gc;
    }
    __syncthreads();

    // ---- Phase 1 (one anchor per thread): division-free IoU max (no index) ----
    float my_reg = 0.0f;
    float my_pos = 0.0f;
    float my_cor = 0.0f;
    {
        const int n = n0 + tid;
        float label = -1.0f;
        if (n < N) {
            const long an = (long)b * N + n;
            const float4 a4 = reinterpret_cast<const float4*>(anchors)[an];
            const float a0 = a4.x, a1 = a4.y, a2 = a4.z, a3 = a4.w;
            const bool inside = (a0 > 0.0f) && (a1 > 0.0f) && (a2 < IMG_W) && (a3 < IMG_H);
            const float area_a = (a2 - a0) * (a3 - a1);

            float bnum = -1.0f, bden = 1.0f;
#pragma unroll
            for (int j = 0; j < MM; j++) {
                const float4 g = sbox[j];
                const float asum = area_a + sarea[j];
                const float lx = fmaxf(a0, g.x), ly = fmaxf(a1, g.y);
                const float rx = fminf(a2, g.z), ry = fminf(a3, g.w);
                const float wx = fmaxf(rx - lx, 0.0f), wy = fmaxf(ry - ly, 0.0f);
                const float num = wx * wy;
                const float den = asum - num;
                if (num * bden > bnum * den) { bnum = num; bden = den; }
            }

            if (bnum < 0.4f * bden) label = 0.0f;
            const bool is_pos = (bnum > 0.5f * bden) && sanyv && inside;
            if (bnum > 0.5f * bden) label = 1.0f;   // provisional; class set below
            if (!sanyv)  label = -1.0f;
            if (!inside) label = -1.0f;

            if (is_pos) {
                // rare path: recompute argmax index with identical tie ordering
                float cn = -1.0f, cd = 1.0f;
                int bidx = 0;
#pragma unroll
                for (int j = 0; j < MM; j++) {
                    const float4 g = sbox[j];
                    const float asum = area_a + sarea[j];
                    const float lx = fmaxf(a0, g.x), ly = fmaxf(a1, g.y);
                    const float rx = fminf(a2, g.z), ry = fminf(a3, g.w);
                    const float wx = fmaxf(rx - lx, 0.0f), wy = fmaxf(ry - ly, 0.0f);
                    const float num = wx * wy;
                    const float den = asum - num;
                    if (num * cd > cn * den) { cn = num; cd = den; bidx = j; }
                }
                label = scls[bidx] + 1.0f;

                const float4 g = sbox[bidx];
                const float aw = a2 - a0, ah = a3 - a1;
                const float acx = a0 + 0.5f * aw, acy = a1 + 0.5f * ah;
                const float gw = fmaxf(g.z - g.x, 1.0f);
                const float gh = fmaxf(g.w - g.y, 1.0f);
                const float gcx = g.x + 0.5f * gw, gcy = g.y + 0.5f * gh;
                const float t0 = ((gcx - acx) / aw) * 10.0f;
                const float t1 = ((gcy - acy) / ah) * 10.0f;
                const float t2 = __logf(gw / aw) * 5.0f;
                const float t3 = __logf(gh / ah) * 5.0f;

                const float4 r4 = reinterpret_cast<const float4*>(regs)[an];
                const float xs[4] = { fabsf(r4.x - t0), fabsf(r4.y - t1),
                                      fabsf(r4.z - t2), fabsf(r4.w - t3) };
#pragma unroll
                for (int k = 0; k < 4; k++) {
                    const float x = xs[k];
                    my_reg += (x < BETA_F) ? (0.5f * x * x / BETA_F) : (x - 0.5f * BETA_F);
                }
                my_pos = 1.0f;

                // correction: true positive focal term minus what the sweep adds
                const int lp = (int)label - 1;
                const float pv = cls[an * CC + lp];
                const float p = fminf(fmaxf(pv, EPS_F), 1.0f - EPS_F);
                const float q = 1.0f - p;
                my_cor = 0.25f * q * q * (-__logf(p)) - 0.75f * pv * pv * (-__logf(1.0f - pv));
            }
        }
        slab[tid] = label;
    }
    __syncthreads();

    // ---- Phase 2: packed negative-focal sweep (f32x2), 2 waves of 10 LDG.128 ----
    const int al = tid >> 2;        // 0..63
    const int lc = tid & 3;
    const float4* __restrict__ base =
        reinterpret_cast<const float4*>(cls) + (long)b * N * C4 + (long)n0 * C4 + lc;

    unsigned long long ones, nones, acc2;
    {
        const float one = 1.0f, mone = -1.0f, zero = 0.0f;
        asm("mov.b64 %0, {%1, %1};" : "=l"(ones)  : "f"(one));
        asm("mov.b64 %0, {%1, %1};" : "=l"(nones) : "f"(mone));
        asm("mov.b64 %0, {%1, %1};" : "=l"(acc2)  : "f"(zero));
    }

#pragma unroll
    for (int w = 0; w < 2; w++) {
        const int a0 = al + w * 128;
        const int a1 = a0 + 64;
        const bool u0 = (slab[a0] >= 0.0f);
        const bool u1 = (slab[a1] >= 0.0f);
        const float4* __restrict__ p0 = base + a0 * C4;
        const float4* __restrict__ p1 = base + a1 * C4;

        float4 v0[5], v1[5];
        if (u0) {
#pragma unroll
            for (int it = 0; it < 5; it++) v0[it] = p0[it * 4];
        }
        if (u1) {
#pragma unroll
            for (int it = 0; it < 5; it++) v1[it] = p1[it * 4];
        }

        if (u0) {
#pragma unroll
            for (int it = 0; it < 5; it++) {
                foc2(v0[it].x, v0[it].y, acc2, nones, ones);
                foc2(v0[it].z, v0[it].w, acc2, nones, ones);
            }
        }
        if (u1) {
#pragma unroll
            for (int it = 0; it < 5; it++) {
                foc2(v1[it].x, v1[it].y, acc2, nones, ones);
                foc2(v1[it].z, v1[it].w, acc2, nones, ones);
            }
        }
    }

    float slo, shi;
    asm("mov.b64 {%0, %1}, %2;" : "=f"(slo), "=f"(shi) : "l"(acc2));
    // negatives: 0.75 * p^2 * (-ln(1-p)) == -0.75*ln2 * sum(p^2 lg2(1-p))
    float acc = fmaf(-0.75f * LN2_F, slo + shi, my_cor);

    // ---- Phase 3: warp shuffle reduce, one barrier, 3 atomics per block ----
#pragma unroll
    for (int o = 16; o; o >>= 1) {
        acc    += __shfl_down_sync(0xffffffffu, acc,    o);
        my_reg += __shfl_down_sync(0xffffffffu, my_reg, o);
        my_pos += __shfl_down_sync(0xffffffffu, my_pos, o);
    }
    const int wid = tid >> 5;
    if ((tid & 31) == 0) {
        swred[wid][0] = acc;
        swred[wid][1] = my_reg;
        swred[wid][2] = my_pos;
    }
    __syncthreads();
    if (tid == 0) {
        float c = 0.0f, r = 0.0f, p = 0.0f;
#pragma unroll
        for (int w = 0; w < 8; w++) {
            c += swred[w][0];
            r += swred[w][1];
            p += swred[w][2];
        }
        if (c != 0.0f) atomicAdd(&g_cls_sum[b], c);
        if (r != 0.0f) atomicAdd(&g_reg_sum[b], r);
        const int pi = (int)(p + 0.5f);
        if (pi) atomicAdd(&g_pos[b], pi);
    }

    // ---- Phase 4: last block finalizes + resets state for next replay ----
    __shared__ bool is_last;
    __threadfence();
    if (tid == 0) {
        const unsigned total = gridDim.x * gridDim.y;
        is_last = (atomicAdd(&g_count, 1u) == total - 1u);
    }
    __syncthreads();
    if (!is_last) return;

    if (tid == 0) {
        float cls_l = 0.0f, reg_l = 0.0f, nvalid = 0.0f;
#pragma unroll
        for (int bi = 0; bi < BB; bi++) {
            const float p = (float)g_pos[bi];
            if (p > 0.0f) {
                cls_l += g_cls_sum[bi] / p;
                reg_l += g_reg_sum[bi] / (4.0f * p);
                nvalid += 1.0f;
            }
            g_cls_sum[bi] = 0.0f;
            g_reg_sum[bi] = 0.0f;
            g_pos[bi] = 0;
        }
        nvalid = fmaxf(nvalid, 1.0f);
        out[0] = cls_l / nvalid;
        out[1] = reg_l / nvalid;
        g_count = 0;
    }
}

extern "C" void kernel_launch(void* const* d_in, const int* in_sizes, int n_in,
                              void* d_out, int out_size) {
    const float* cls     = (const float*)d_in[0];  // (B, N, C)
    const float* regs    = (const float*)d_in[1];  // (B, N, 4)
    const float* anchors = (const float*)d_in[2];  // (B, N, 4)
    const float* annots  = (const float*)d_in[3];  // (B, M, 5)

    const int N = in_sizes[1] / (BB * 4);
    const int numTiles = (N + TILE - 1) / TILE;

    dim3 grid(numTiles, BB);
    retina_fused_kernel<<<grid, THREADS>>>(cls, regs, anchors, annots,
                                           (float*)d_out, N);
}